// round 1
// baseline (speedup 1.0000x reference)
#include <cuda_runtime.h>
#include <math_constants.h>

#define N_ROWS 32768
#define D_DIM  256
#define K_CODES 1024

#define BM 128
#define BN 128
#define BK 16

// -------- scratch (no allocations allowed) --------
__device__ float  g_a[N_ROWS];     // ||z_n||^2
__device__ float  g_b[K_CODES];    // ||e_k||^2
__device__ int    g_idx[N_ROWS];   // argmin code per row
__device__ double g_part[64];      // loss partial sums

// -------- packed f32x2 helpers --------
__device__ __forceinline__ unsigned long long fma_f32x2(unsigned long long a,
                                                        unsigned long long b,
                                                        unsigned long long c) {
    unsigned long long d;
    asm("fma.rn.f32x2 %0, %1, %2, %3;" : "=l"(d) : "l"(a), "l"(b), "l"(c));
    return d;
}
__device__ __forceinline__ unsigned long long pack2(float lo, float hi) {
    unsigned long long r;
    asm("mov.b64 %0, {%1, %2};" : "=l"(r) : "f"(lo), "f"(hi));
    return r;
}
__device__ __forceinline__ void unpack2(unsigned long long v, float& lo, float& hi) {
    asm("mov.b64 {%0, %1}, %2;" : "=f"(lo), "=f"(hi) : "l"(v));
}

// ============ kernel 1: row norms for z and emb, zero loss partials ============
__global__ void prep_norms(const float* __restrict__ z, const float* __restrict__ emb) {
    int warp = (blockIdx.x * blockDim.x + threadIdx.x) >> 5;
    int lane = threadIdx.x & 31;
    if (blockIdx.x == 0 && threadIdx.x < 64) g_part[threadIdx.x] = 0.0;

    const float* src;
    float* dst;
    if (warp < N_ROWS) {
        src = z + (size_t)warp * D_DIM;
        dst = g_a + warp;
    } else if (warp < N_ROWS + K_CODES) {
        src = emb + (size_t)(warp - N_ROWS) * D_DIM;
        dst = g_b + (warp - N_ROWS);
    } else {
        return;
    }
    float s = 0.f;
#pragma unroll
    for (int i = 0; i < D_DIM / 32; i++) {
        float v = src[lane + i * 32];
        s = __fmaf_rn(v, v, s);
    }
#pragma unroll
    for (int o = 16; o > 0; o >>= 1) s = __fadd_rn(s, __shfl_down_sync(0xffffffffu, s, o));
    if (lane == 0) *dst = s;
}

// ============ kernel 2: fused fp32 dist-GEMM + argmin ============
// dist(n,k) = fl(fl(a_n + b_k) - 2*dot) matching the reference's fp32 elementwise rounding.
__global__ __launch_bounds__(256, 2)
void gemm_argmin(const float* __restrict__ z, const float* __restrict__ emb) {
    __shared__ float zs[BK][BM];   // k-major z tile
    __shared__ float es[BK][BN];   // k-major emb tile
    __shared__ float sh_a[BM];
    __shared__ float sh_b[BN];
    __shared__ float best_d[BM];
    __shared__ int   best_i[BM];

    const int tid = threadIdx.x;
    const int tx = tid & 15;        // code group 0..15
    const int ty = tid >> 4;        // row  group 0..15
    const int n0 = blockIdx.x * BM;

    if (tid < BM) {
        best_d[tid] = CUDART_INF_F;
        best_i[tid] = 0;
        sh_a[tid] = g_a[n0 + tid];
    }

    for (int c0 = 0; c0 < K_CODES; c0 += BN) {
        if (tid < BN) sh_b[tid] = g_b[c0 + tid];

        // acc[p][j]: rows (ty*8+2p, ty*8+2p+1) x code (c0+tx*8+j), packed f32x2
        unsigned long long acc[4][8];
#pragma unroll
        for (int p = 0; p < 4; p++)
#pragma unroll
            for (int j = 0; j < 8; j++) acc[p][j] = 0ull;

        for (int k0 = 0; k0 < D_DIM; k0 += BK) {
            __syncthreads();
            // load tiles: 128 rows x 16 k each, as float4, scatter to k-major smem
#pragma unroll
            for (int it = 0; it < 2; it++) {
                int f = tid + it * 256;
                int row = f >> 2;
                int kq = (f & 3) * 4;
                float4 v = *reinterpret_cast<const float4*>(&z[(size_t)(n0 + row) * D_DIM + k0 + kq]);
                zs[kq + 0][row] = v.x; zs[kq + 1][row] = v.y;
                zs[kq + 2][row] = v.z; zs[kq + 3][row] = v.w;
                float4 w = *reinterpret_cast<const float4*>(&emb[(size_t)(c0 + row) * D_DIM + k0 + kq]);
                es[kq + 0][row] = w.x; es[kq + 1][row] = w.y;
                es[kq + 2][row] = w.z; es[kq + 3][row] = w.w;
            }
            __syncthreads();

#pragma unroll
            for (int kk = 0; kk < BK; kk++) {
                unsigned long long zf[4];
#pragma unroll
                for (int p = 0; p < 4; p++)
                    zf[p] = *reinterpret_cast<const unsigned long long*>(&zs[kk][ty * 8 + 2 * p]);
                float4 e0 = *reinterpret_cast<const float4*>(&es[kk][tx * 8]);
                float4 e1 = *reinterpret_cast<const float4*>(&es[kk][tx * 8 + 4]);
                float ef[8] = {e0.x, e0.y, e0.z, e0.w, e1.x, e1.y, e1.z, e1.w};
#pragma unroll
                for (int j = 0; j < 8; j++) {
                    unsigned long long eb = pack2(ef[j], ef[j]);
#pragma unroll
                    for (int p = 0; p < 4; p++)
                        acc[p][j] = fma_f32x2(zf[p], eb, acc[p][j]);
                }
            }
        }

        // ---- epilogue: dist + argmin for this code tile ----
#pragma unroll
        for (int p = 0; p < 4; p++) {
#pragma unroll
            for (int h = 0; h < 2; h++) {
                int i = 2 * p + h;
                float a_s = sh_a[ty * 8 + i];
                float bdv = CUDART_INF_F;
                int biv = 0;
#pragma unroll
                for (int j = 0; j < 8; j++) {
                    float lo, hi;
                    unpack2(acc[p][j], lo, hi);
                    float c = h ? hi : lo;
                    float s = __fadd_rn(a_s, sh_b[tx * 8 + j]);
                    float dd = __fmaf_rn(-2.0f, c, s);
                    if (dd < bdv) { bdv = dd; biv = c0 + tx * 8 + j; }
                }
                // reduce over the 16 lanes sharing this row group (half-warp)
#pragma unroll
                for (int o = 8; o > 0; o >>= 1) {
                    float od = __shfl_down_sync(0xffffffffu, bdv, o, 16);
                    int   oi = __shfl_down_sync(0xffffffffu, biv, o, 16);
                    if (od < bdv || (od == bdv && oi < biv)) { bdv = od; biv = oi; }
                }
                if (tx == 0) {
                    int row = ty * 8 + i;
                    if (bdv < best_d[row] || (bdv == best_d[row] && biv < best_i[row])) {
                        best_d[row] = bdv;
                        best_i[row] = biv;
                    }
                }
            }
        }
        __syncthreads();   // protect sh_b / smem tiles before next code tile
    }

    if (tid < BM) g_idx[n0 + tid] = best_i[tid];
}

// ============ kernel 3: gather + straight-through output + MSE partial sums ============
__global__ void finalize_out(const float* __restrict__ z, const float* __restrict__ emb,
                             float* __restrict__ out) {
    int t = blockIdx.x * 256 + threadIdx.x;   // one float4 per thread
    int base = t * 4;
    int n = base >> 8;
    int d0 = base & 255;
    int code = g_idx[n];

    float4 q  = *reinterpret_cast<const float4*>(&emb[(size_t)code * D_DIM + d0]);
    float4 zv = *reinterpret_cast<const float4*>(&z[(size_t)base]);

    float dx = __fadd_rn(q.x, -zv.x);
    float dy = __fadd_rn(q.y, -zv.y);
    float dz = __fadd_rn(q.z, -zv.z);
    float dw = __fadd_rn(q.w, -zv.w);

    float4 ov;
    ov.x = __fadd_rn(zv.x, dx);
    ov.y = __fadd_rn(zv.y, dy);
    ov.z = __fadd_rn(zv.z, dz);
    ov.w = __fadd_rn(zv.w, dw);
    *reinterpret_cast<float4*>(&out[(size_t)base]) = ov;

    double s = (double)dx * dx + (double)dy * dy + (double)dz * dz + (double)dw * dw;
#pragma unroll
    for (int o = 16; o > 0; o >>= 1) s += __shfl_down_sync(0xffffffffu, s, o);

    __shared__ double ws[8];
    int lane = threadIdx.x & 31, wid = threadIdx.x >> 5;
    if (lane == 0) ws[wid] = s;
    __syncthreads();
    if (threadIdx.x == 0) {
        double bs = 0.0;
#pragma unroll
        for (int w = 0; w < 8; w++) bs += ws[w];
        atomicAdd(&g_part[blockIdx.x & 63], bs);
    }
}

// ============ kernel 4: final loss ============
__global__ void loss_final(float* __restrict__ out, int out_size) {
    if (threadIdx.x == 0 && blockIdx.x == 0) {
        double s = 0.0;
        for (int i = 0; i < 64; i++) s += g_part[i];
        double m = s / (double)((size_t)N_ROWS * D_DIM);
        float mf = (float)m;
        out[out_size - 1] = __fadd_rn(mf, __fmul_rn(0.25f, mf));
    }
}

extern "C" void kernel_launch(void* const* d_in, const int* in_sizes, int n_in,
                              void* d_out, int out_size) {
    const float* z   = (const float*)d_in[0];
    const float* emb = (const float*)d_in[1];
    float* out = (float*)d_out;

    // 1) norms (33792 warps) + zero partials
    prep_norms<<<(N_ROWS + K_CODES) / 8, 256>>>(z, emb);
    // 2) fused distance GEMM + argmin
    gemm_argmin<<<N_ROWS / BM, 256>>>(z, emb);
    // 3) gather + STE output + loss partials
    finalize_out<<<(N_ROWS * D_DIM) / (256 * 4), 256>>>(z, emb, out);
    // 4) loss scalar
    loss_final<<<1, 32>>>(out, out_size);
}